// round 4
// baseline (speedup 1.0000x reference)
#include <cuda_runtime.h>

// MessagePassing tree DP on a deterministic 4-ary heap tree.
// B=64, C=2, L=4096. Child s in [1,L) has parent (s-1)>>2.
// Level starts: (4^k-1)/3 = 0,1,5,21,85,341,1365 (leaves clipped at 4096).
//
// One CTA per batch. Message state msg[2][4096] (32 KB) in static shared.
// All transitions gathers are data-independent -> prefetched into REGISTERS
// at kernel start (<=12 float4 per thread, MLP=12), so the 6-level dependency
// chain touches only shared memory. Parent emissions (nodes 0..1023) staged
// into shared coalesced. Only msg[0] needs zero-init (every other node is
// written exactly once before any read).

#define LNODES 4096
#define NT 512

__device__ __forceinline__ float lse2(float a, float b) {
    float m = fmaxf(a, b);
    return m + log1pf(__expf(-fabsf(a - b)));
}

__global__ __launch_bounds__(NT, 1)
void mp_tree_kernel(const float* __restrict__ em,   // [B, 2, L]
                    const float* __restrict__ tr,   // [L, L, 2, 2]
                    float* __restrict__ out)        // [B, 2, L]
{
    __shared__ float msg0[LNODES];
    __shared__ float msg1[LNODES];
    __shared__ float em0[1024];   // emissions[b,0,p] for parents p in [0,1024)
    __shared__ float em1[1024];   // emissions[b,1,p]

    const int  tid = threadIdx.x;
    const int  b   = blockIdx.x;
    const float* eb = em + (size_t)b * 2 * LNODES;

    constexpr int starts[8] = {0, 1, 5, 21, 85, 341, 1365, 5461};
    constexpr int iters[8]  = {0, 1, 1, 1, 1, 2, 6, 0};  // ceil(edges/NT) per level

    // ---- Phase 0a: issue ALL transitions gathers up front (registers) ----
    float4 t[12];
    {
        int k = 0;
        #pragma unroll
        for (int lev = 1; lev <= 6; lev++) {
            const int s1 = (starts[lev + 1] < LNODES) ? starts[lev + 1] : LNODES;
            #pragma unroll
            for (int i = 0; i < iters[lev]; i++) {
                const int s = starts[lev] + i * NT + tid;
                if (s < s1) {
                    const int p = (s - 1) >> 2;
                    t[k] = __ldg((const float4*)(tr + ((size_t)s * LNODES + p) * 4));
                }
                k++;
            }
        }
    }

    // ---- Phase 0b: stage parent emissions into shared; zero msg[0] ----
    #pragma unroll
    for (int i = 0; i < 2; i++) {
        const int p = i * NT + tid;
        em0[p] = __ldg(eb + p);
        em1[p] = __ldg(eb + LNODES + p);
    }
    if (tid == 0) { msg0[0] = 0.0f; msg1[0] = 0.0f; }
    __syncthreads();

    // ---- Phase 1: level sweep, pure shared-memory dependency chain ----
    {
        int k = 0;
        #pragma unroll
        for (int lev = 1; lev <= 6; lev++) {
            const int s1 = (starts[lev + 1] < LNODES) ? starts[lev + 1] : LNODES;
            #pragma unroll
            for (int i = 0; i < iters[lev]; i++) {
                const int s = starts[lev] + i * NT + tid;
                if (s < s1) {
                    const int p = (s - 1) >> 2;
                    const float l0 = em0[p] + msg0[p];
                    const float l1 = em1[p] + msg1[p];
                    const float4 tt = t[k];
                    msg0[s] = lse2(l0 + tt.x, l1 + tt.y);
                    msg1[s] = lse2(l0 + tt.z, l1 + tt.w);
                }
                k++;
            }
            __syncthreads();
        }
    }

    // ---- Phase 2: vectorized writeback (covers poisoned d_out; root = 0) ----
    float4* ob0 = (float4*)(out + (size_t)b * 2 * LNODES);
    float4* ob1 = (float4*)(out + (size_t)b * 2 * LNODES + LNODES);
    const float4* m0 = (const float4*)msg0;
    const float4* m1 = (const float4*)msg1;
    #pragma unroll
    for (int i = 0; i < 2; i++) {
        const int j = i * NT + tid;   // 1024 float4 per class
        ob0[j] = m0[j];
        ob1[j] = m1[j];
    }
}

extern "C" void kernel_launch(void* const* d_in, const int* in_sizes, int n_in,
                              void* d_out, int out_size) {
    const float* em = (const float*)d_in[0];  // emissions   [64, 2, 4096] f32
    const float* tr = (const float*)d_in[1];  // transitions [4096,4096,2,2] f32
    (void)in_sizes; (void)n_in; (void)out_size;
    mp_tree_kernel<<<64, NT>>>(em, tr, (float*)d_out);
}